// round 6
// baseline (speedup 1.0000x reference)
#include <cuda_runtime.h>
#include <cstddef>

typedef unsigned long long ull;

// ---------------- scratch (static device globals; no allocation) ----------------
__device__ float g_h64[4096 * 64];     // LSTM1 final hidden
__device__ float g_h256[4096 * 256];   // LSTM2 hidden

// ---------------- packed f32x2 helpers ----------------
__device__ __forceinline__ ull pk(float lo, float hi) {
    ull r;
    asm("mov.b64 %0, {%1, %2};" : "=l"(r) : "f"(lo), "f"(hi));
    return r;
}
__device__ __forceinline__ void fma2(ull& d, ull a, ull b) {
    asm("fma.rn.f32x2 %0, %1, %2, %0;" : "+l"(d) : "l"(a), "l"(b));
}
__device__ __forceinline__ void add2(ull& d, ull a) {
    asm("add.rn.f32x2 %0, %0, %1;" : "+l"(d) : "l"(a));
}
__device__ __forceinline__ float2 upk(ull v) {
    float2 r;
    asm("mov.b64 {%0, %1}, %2;" : "=f"(r.x), "=f"(r.y) : "l"(v));
    return r;
}

// accurate activations (expf ~2ulp) — measured rel_err 2e-6 with these
__device__ __forceinline__ float sigf(float x) {
    return __fdividef(1.0f, 1.0f + __expf(-x));
}
__device__ __forceinline__ float tanh_(float x) {
    return __fdividef(2.0f, 1.0f + __expf(-2.0f * x)) - 1.0f;
}

// ---------------- shared layout for LSTM1 (float offsets) ----------------
// Wsh  [84][256]  : 21504  (k-major; column = type*64 + j, types i|f|g|o)
// actA [84][68]   :  5712  (rows 0..19 emb, 20..83 h; DUPLICATED [2b],[2b+1])
// actB [84][68]   :  5712
// bsh  [256]      :   256
// eW   [64]       :    64
// Ebuf [128][34]  :  8704  (ull; E(t) = bias + emb-part, pair-major)
// Pbuf [128][34]  :  8704  (ull; group-1 h-part partials)
#define AROW   68
#define S_WSH  0
#define S_ACT0 21504
#define S_ACT1 (S_ACT0 + 5712)
#define S_BSH  (S_ACT1 + 5712)
#define S_EW   (S_BSH + 256)
#define S_EBUF (S_EW + 64)           // 33248 (16B aligned)
#define S_PBUF (S_EBUF + 8704)       // 41952 (16B aligned)
#define S_TOT  (S_PBUF + 8704)       // 50656 floats = 202624 B

__global__ void __launch_bounds__(512, 1)
lstm1_kernel(const float* __restrict__ x,
             const float* __restrict__ W_embed,
             const float* __restrict__ Wih1,
             const float* __restrict__ Whh1,
             const float* __restrict__ b1)
{
    extern __shared__ float sm[];
    float* Wsh  = sm + S_WSH;
    float* act0 = sm + S_ACT0;
    float* act1 = sm + S_ACT1;
    float* bsh  = sm + S_BSH;
    float* eW   = sm + S_EW;
    ull*   Ebuf = reinterpret_cast<ull*>(sm + S_EBUF);
    ull*   Pbuf = reinterpret_cast<ull*>(sm + S_PBUF);

    const int tid = threadIdx.x;
    const int bt  = blockIdx.x;          // batch tile (32 elems)

    // combined weight [k][col]: col = gate (i|f|g|o each 64 wide)
    for (int idx = tid; idx < 84 * 256; idx += 512) {
        int k = idx >> 8, g = idx & 255;
        Wsh[idx] = (k < 20) ? __ldg(&Wih1[g * 20 + k])
                            : __ldg(&Whh1[g * 64 + (k - 20)]);
    }
    if (tid < 256) bsh[tid] = b1[tid];
    if (tid < 40)  eW[tid]  = W_embed[tid];
    // zero h rows of act0 (incl. dup slots + pad)
    for (int idx = tid; idx < 64 * AROW; idx += 512) act0[20 * AROW + idx] = 0.0f;
    __syncthreads();

    // ---- mapping ----
    // warp w: wg = w>>3 (k-group), wl = w&7; g2 = wl&3 (batch octet), jh = wl>>2
    // lane: j0 = jh*32 + 2*(l&15)  (gate pair), b0 = g2*8 + 4*(l>>4) (batch quad)
    const int w  = tid >> 5, l = tid & 31;
    const int wg = w >> 3,  wl = w & 7;
    const int g2 = wl & 3,  jh = wl >> 2;
    const int j0 = jh * 32 + 2 * (l & 15);
    const int b0 = g2 * 8 + 4 * (l >> 4);
    const int pj = j0 >> 1;              // pair index within 32

    const float* wIb = Wsh + j0;
    const float* wFb = Wsh + 64 + j0;
    const float* wGb = Wsh + 128 + j0;
    const float* wOb = Wsh + 192 + j0;

    const ull bI = pk(bsh[j0],       bsh[j0 + 1]);
    const ull bF = pk(bsh[64 + j0],  bsh[64 + j0 + 1]);
    const ull bG = pk(bsh[128 + j0], bsh[128 + j0 + 1]);
    const ull bO = pk(bsh[192 + j0], bsh[192 + j0 + 1]);

    // ull-pair buffer bases for this thread (conflict-free: stride 34 ull/lane)
    ull* EI = Ebuf + (0  + pj) * 34 + b0;
    ull* EF = Ebuf + (32 + pj) * 34 + b0;
    ull* EG = Ebuf + (64 + pj) * 34 + b0;
    ull* EO = Ebuf + (96 + pj) * 34 + b0;
    ull* PI = Pbuf + (0  + pj) * 34 + b0;
    ull* PF = Pbuf + (32 + pj) * 34 + b0;
    ull* PG = Pbuf + (64 + pj) * 34 + b0;
    ull* PO = Pbuf + (96 + pj) * 34 + b0;

    // cell state (group 0 only): c[b 0..3][j 0..1]
    float c0x=0.f,c0y=0.f,c1x=0.f,c1y=0.f,c2x=0.f,c2y=0.f,c3x=0.f,c3y=0.f;

    // embedding duty (group 1): warp wl owns batches wl*4 .. wl*4+3
    const int eb0 = wl * 4;
    const float2* xrow = reinterpret_cast<const float2*>(x) +
                         (size_t)(bt * 32 + eb0 + l) * 512;   // valid for l<4
    float2 tok_nxt = make_float2(0.f, 0.f);

    // ---- prologue: emb(0) + E(0) (group 1) ----
    if (wg == 1) {
        float2 t0 = make_float2(0.f, 0.f);
        if (l < 4) t0 = xrow[0];
        #pragma unroll
        for (int b = 0; b < 4; b++) {
            float tx = __shfl_sync(0xffffffffu, t0.x, b);
            float ty = __shfl_sync(0xffffffffu, t0.y, b);
            if (l < 20) {
                float v = fmaxf(fmaf(tx, eW[2 * l], ty * eW[2 * l + 1]), 0.0f);
                *reinterpret_cast<float2*>(act0 + l * AROW + 2 * (eb0 + b)) =
                    make_float2(v, v);
            }
        }
        if (l < 4) tok_nxt = xrow[1];
        asm volatile("bar.sync 1, 256;" ::: "memory");
        // E(0) = bias + emb(0) @ W[0:20]
        ull eI0=bI,eI1=bI,eI2=bI,eI3=bI, eF0=bF,eF1=bF,eF2=bF,eF3=bF;
        ull eG0=bG,eG1=bG,eG2=bG,eG3=bG, eO0=bO,eO1=bO,eO2=bO,eO3=bO;
        const float* ab = act0 + 2 * b0;
        #pragma unroll 10
        for (int k = 0; k < 20; k++) {
            ulonglong2 a01 = *reinterpret_cast<const ulonglong2*>(ab + k * AROW);
            ulonglong2 a23 = *reinterpret_cast<const ulonglong2*>(ab + k * AROW + 4);
            ull wi = *reinterpret_cast<const ull*>(wIb + k * 256);
            ull wf = *reinterpret_cast<const ull*>(wFb + k * 256);
            ull wgv= *reinterpret_cast<const ull*>(wGb + k * 256);
            ull wo = *reinterpret_cast<const ull*>(wOb + k * 256);
            fma2(eI0,wi,a01.x); fma2(eI1,wi,a01.y); fma2(eI2,wi,a23.x); fma2(eI3,wi,a23.y);
            fma2(eF0,wf,a01.x); fma2(eF1,wf,a01.y); fma2(eF2,wf,a23.x); fma2(eF3,wf,a23.y);
            fma2(eG0,wgv,a01.x);fma2(eG1,wgv,a01.y);fma2(eG2,wgv,a23.x);fma2(eG3,wgv,a23.y);
            fma2(eO0,wo,a01.x); fma2(eO1,wo,a01.y); fma2(eO2,wo,a23.x); fma2(eO3,wo,a23.y);
        }
        *reinterpret_cast<ulonglong2*>(EI)     = make_ulonglong2(eI0, eI1);
        *reinterpret_cast<ulonglong2*>(EI + 2) = make_ulonglong2(eI2, eI3);
        *reinterpret_cast<ulonglong2*>(EF)     = make_ulonglong2(eF0, eF1);
        *reinterpret_cast<ulonglong2*>(EF + 2) = make_ulonglong2(eF2, eF3);
        *reinterpret_cast<ulonglong2*>(EG)     = make_ulonglong2(eG0, eG1);
        *reinterpret_cast<ulonglong2*>(EG + 2) = make_ulonglong2(eG2, eG3);
        *reinterpret_cast<ulonglong2*>(EO)     = make_ulonglong2(eO0, eO1);
        *reinterpret_cast<ulonglong2*>(EO + 2) = make_ulonglong2(eO2, eO3);
    }
    __syncthreads();

    // ---- main loop ----
    for (int t = 0; t < 512; t++) {
        float* cur = (t & 1) ? act1 : act0;
        float* nxt = (t & 1) ? act0 : act1;

        if (wg == 0) {
            // ===== phase A (group 0): acc = E(t), += h-part k=20..51 =====
            ulonglong2 e;
            ull aI0,aI1,aI2,aI3,aF0,aF1,aF2,aF3,aG0,aG1,aG2,aG3,aO0,aO1,aO2,aO3;
            e = *reinterpret_cast<const ulonglong2*>(EI);     aI0=e.x; aI1=e.y;
            e = *reinterpret_cast<const ulonglong2*>(EI + 2); aI2=e.x; aI3=e.y;
            e = *reinterpret_cast<const ulonglong2*>(EF);     aF0=e.x; aF1=e.y;
            e = *reinterpret_cast<const ulonglong2*>(EF + 2); aF2=e.x; aF3=e.y;
            e = *reinterpret_cast<const ulonglong2*>(EG);     aG0=e.x; aG1=e.y;
            e = *reinterpret_cast<const ulonglong2*>(EG + 2); aG2=e.x; aG3=e.y;
            e = *reinterpret_cast<const ulonglong2*>(EO);     aO0=e.x; aO1=e.y;
            e = *reinterpret_cast<const ulonglong2*>(EO + 2); aO2=e.x; aO3=e.y;

            const float* ab = cur + 2 * b0;
            #pragma unroll 8
            for (int k = 20; k < 52; k++) {
                ulonglong2 a01 = *reinterpret_cast<const ulonglong2*>(ab + k * AROW);
                ulonglong2 a23 = *reinterpret_cast<const ulonglong2*>(ab + k * AROW + 4);
                ull wi = *reinterpret_cast<const ull*>(wIb + k * 256);
                ull wf = *reinterpret_cast<const ull*>(wFb + k * 256);
                ull wgv= *reinterpret_cast<const ull*>(wGb + k * 256);
                ull wo = *reinterpret_cast<const ull*>(wOb + k * 256);
                fma2(aI0,wi,a01.x); fma2(aI1,wi,a01.y); fma2(aI2,wi,a23.x); fma2(aI3,wi,a23.y);
                fma2(aF0,wf,a01.x); fma2(aF1,wf,a01.y); fma2(aF2,wf,a23.x); fma2(aF3,wf,a23.y);
                fma2(aG0,wgv,a01.x);fma2(aG1,wgv,a01.y);fma2(aG2,wgv,a23.x);fma2(aG3,wgv,a23.y);
                fma2(aO0,wo,a01.x); fma2(aO1,wo,a01.y); fma2(aO2,wo,a23.x); fma2(aO3,wo,a23.y);
            }
            __syncthreads();   // barrier 1: group-1 partials ready

            // ===== phase B (group 0): combine partials + pointwise =====
            e = *reinterpret_cast<const ulonglong2*>(PI);     add2(aI0,e.x); add2(aI1,e.y);
            e = *reinterpret_cast<const ulonglong2*>(PI + 2); add2(aI2,e.x); add2(aI3,e.y);
            e = *reinterpret_cast<const ulonglong2*>(PF);     add2(aF0,e.x); add2(aF1,e.y);
            e = *reinterpret_cast<const ulonglong2*>(PF + 2); add2(aF2,e.x); add2(aF3,e.y);
            e = *reinterpret_cast<const ulonglong2*>(PG);     add2(aG0,e.x); add2(aG1,e.y);
            e = *reinterpret_cast<const ulonglong2*>(PG + 2); add2(aG2,e.x); add2(aG3,e.y);
            e = *reinterpret_cast<const ulonglong2*>(PO);     add2(aO0,e.x); add2(aO1,e.y);
            e = *reinterpret_cast<const ulonglong2*>(PO + 2); add2(aO2,e.x); add2(aO3,e.y);

            float2 vi, vf, vg, vo;
            float h0x,h0y,h1x,h1y,h2x,h2y,h3x,h3y;
            vi=upk(aI0); vf=upk(aF0); vg=upk(aG0); vo=upk(aO0);
            c0x = fmaf(sigf(vf.x), c0x, sigf(vi.x) * tanh_(vg.x));
            h0x = sigf(vo.x) * tanh_(c0x);
            c0y = fmaf(sigf(vf.y), c0y, sigf(vi.y) * tanh_(vg.y));
            h0y = sigf(vo.y) * tanh_(c0y);
            vi=upk(aI1); vf=upk(aF1); vg=upk(aG1); vo=upk(aO1);
            c1x = fmaf(sigf(vf.x), c1x, sigf(vi.x) * tanh_(vg.x));
            h1x = sigf(vo.x) * tanh_(c1x);
            c1y = fmaf(sigf(vf.y), c1y, sigf(vi.y) * tanh_(vg.y));
            h1y = sigf(vo.y) * tanh_(c1y);
            vi=upk(aI2); vf=upk(aF2); vg=upk(aG2); vo=upk(aO2);
            c2x = fmaf(sigf(vf.x), c2x, sigf(vi.x) * tanh_(vg.x));
            h2x = sigf(vo.x) * tanh_(c2x);
            c2y = fmaf(sigf(vf.y), c2y, sigf(vi.y) * tanh_(vg.y));
            h2y = sigf(vo.y) * tanh_(c2y);
            vi=upk(aI3); vf=upk(aF3); vg=upk(aG3); vo=upk(aO3);
            c3x = fmaf(sigf(vf.x), c3x, sigf(vi.x) * tanh_(vg.x));
            h3x = sigf(vo.x) * tanh_(c3x);
            c3y = fmaf(sigf(vf.y), c3y, sigf(vi.y) * tanh_(vg.y));
            h3y = sigf(vo.y) * tanh_(c3y);

            *reinterpret_cast<float4*>(nxt + (20 + j0) * AROW + 2 * b0) =
                make_float4(h0x, h0x, h1x, h1x);
            *reinterpret_cast<float4*>(nxt + (20 + j0) * AROW + 2 * b0 + 4) =
                make_float4(h2x, h2x, h3x, h3x);
            *reinterpret_cast<float4*>(nxt + (21 + j0) * AROW + 2 * b0) =
                make_float4(h0y, h0y, h1y, h1y);
            *reinterpret_cast<float4*>(nxt + (21 + j0) * AROW + 2 * b0 + 4) =
                make_float4(h2y, h2y, h3y, h3y);
        } else {
            // ===== phase A (group 1): h-part k=52..83 -> Pbuf =====
            ull aI0=0,aI1=0,aI2=0,aI3=0,aF0=0,aF1=0,aF2=0,aF3=0;
            ull aG0=0,aG1=0,aG2=0,aG3=0,aO0=0,aO1=0,aO2=0,aO3=0;
            const float* ab = cur + 2 * b0;
            #pragma unroll 8
            for (int k = 52; k < 84; k++) {
                ulonglong2 a01 = *reinterpret_cast<const ulonglong2*>(ab + k * AROW);
                ulonglong2 a23 = *reinterpret_cast<const ulonglong2*>(ab + k * AROW + 4);
                ull wi = *reinterpret_cast<const ull*>(wIb + k * 256);
                ull wf = *reinterpret_cast<const ull*>(wFb + k * 256);
                ull wgv= *reinterpret_cast<const ull*>(wGb + k * 256);
                ull wo = *reinterpret_cast<const ull*>(wOb + k * 256);
                fma2(aI0,wi,a01.x); fma2(aI1,wi,a01.y); fma2(aI2,wi,a23.x); fma2(aI3,wi,a23.y);
                fma2(aF0,wf,a01.x); fma2(aF1,wf,a01.y); fma2(aF2,wf,a23.x); fma2(aF3,wf,a23.y);
                fma2(aG0,wgv,a01.x);fma2(aG1,wgv,a01.y);fma2(aG2,wgv,a23.x);fma2(aG3,wgv,a23.y);
                fma2(aO0,wo,a01.x); fma2(aO1,wo,a01.y); fma2(aO2,wo,a23.x); fma2(aO3,wo,a23.y);
            }
            *reinterpret_cast<ulonglong2*>(PI)     = make_ulonglong2(aI0, aI1);
            *reinterpret_cast<ulonglong2*>(PI + 2) = make_ulonglong2(aI2, aI3);
            *reinterpret_cast<ulonglong2*>(PF)     = make_ulonglong2(aF0, aF1);
            *reinterpret_cast<ulonglong2*>(PF + 2) = make_ulonglong2(aF2, aF3);
            *reinterpret_cast<ulonglong2*>(PG)     = make_ulonglong2(aG0, aG1);
            *reinterpret_cast<ulonglong2*>(PG + 2) = make_ulonglong2(aG2, aG3);
            *reinterpret_cast<ulonglong2*>(PO)     = make_ulonglong2(aO0, aO1);
            *reinterpret_cast<ulonglong2*>(PO + 2) = make_ulonglong2(aO2, aO3);
            __syncthreads();   // barrier 1

            // ===== phase B (group 1): emb(t+1) + E(t+1), overlapped with group-0 MUFU =====
            if (t < 511) {
                #pragma unroll
                for (int b = 0; b < 4; b++) {
                    float tx = __shfl_sync(0xffffffffu, tok_nxt.x, b);
                    float ty = __shfl_sync(0xffffffffu, tok_nxt.y, b);
                    if (l < 20) {
                        float v = fmaxf(fmaf(tx, eW[2 * l], ty * eW[2 * l + 1]), 0.0f);
                        *reinterpret_cast<float2*>(nxt + l * AROW + 2 * (eb0 + b)) =
                            make_float2(v, v);
                    }
                }
                if (l < 4 && t < 510) tok_nxt = xrow[t + 2];
                asm volatile("bar.sync 1, 256;" ::: "memory");

                ull eI0=bI,eI1=bI,eI2=bI,eI3=bI, eF0=bF,eF1=bF,eF2=bF,eF3=bF;
                ull eG0=bG,eG1=bG,eG2=bG,eG3=bG, eO0=bO,eO1=bO,eO2=bO,eO3=bO;
                const float* abn = nxt + 2 * b0;
                #pragma unroll 10
                for (int k = 0; k < 20; k++) {
                    ulonglong2 a01 = *reinterpret_cast<const ulonglong2*>(abn + k * AROW);
                    ulonglong2 a23 = *reinterpret_cast<const ulonglong2*>(abn + k * AROW + 4);
                    ull wi = *reinterpret_cast<const ull*>(wIb + k * 256);
                    ull wf = *reinterpret_cast<const ull*>(wFb + k * 256);
                    ull wgv= *reinterpret_cast<const ull*>(wGb + k * 256);
                    ull wo = *reinterpret_cast<const ull*>(wOb + k * 256);
                    fma2(eI0,wi,a01.x); fma2(eI1,wi,a01.y); fma2(eI2,wi,a23.x); fma2(eI3,wi,a23.y);
                    fma2(eF0,wf,a01.x); fma2(eF1,wf,a01.y); fma2(eF2,wf,a23.x); fma2(eF3,wf,a23.y);
                    fma2(eG0,wgv,a01.x);fma2(eG1,wgv,a01.y);fma2(eG2,wgv,a23.x);fma2(eG3,wgv,a23.y);
                    fma2(eO0,wo,a01.x); fma2(eO1,wo,a01.y); fma2(eO2,wo,a23.x); fma2(eO3,wo,a23.y);
                }
                *reinterpret_cast<ulonglong2*>(EI)     = make_ulonglong2(eI0, eI1);
                *reinterpret_cast<ulonglong2*>(EI + 2) = make_ulonglong2(eI2, eI3);
                *reinterpret_cast<ulonglong2*>(EF)     = make_ulonglong2(eF0, eF1);
                *reinterpret_cast<ulonglong2*>(EF + 2) = make_ulonglong2(eF2, eF3);
                *reinterpret_cast<ulonglong2*>(EG)     = make_ulonglong2(eG0, eG1);
                *reinterpret_cast<ulonglong2*>(EG + 2) = make_ulonglong2(eG2, eG3);
                *reinterpret_cast<ulonglong2*>(EO)     = make_ulonglong2(eO0, eO1);
                *reinterpret_cast<ulonglong2*>(EO + 2) = make_ulonglong2(eO2, eO3);
            }
        }
        __syncthreads();   // barrier 2: act(t+1) + E(t+1) complete
    }

    // final h (after step 512) lives in act0 (t=511 odd -> nxt=act0)
    for (int idx = tid; idx < 2048; idx += 512) {
        int bb = idx >> 6, j = idx & 63;
        g_h64[(size_t)(bt * 32 + bb) * 64 + j] = act0[(20 + j) * AROW + 2 * bb];
    }
}

// ---------------- LSTM2: single step, zero state -> f gate & Whh2 unused ----------------
__global__ void __launch_bounds__(256, 1)
lstm2_kernel(const float* __restrict__ Wih2, const float* __restrict__ b2)
{
    extern __shared__ float sm[];
    float* Ws   = sm;            // [type][k][j], type 0:i 1:g 2:o
    float* hact = sm + 49152;    // [k][b]
    const int tid = threadIdx.x;
    const int bt  = blockIdx.x;

    for (int idx = tid; idx < 3 * 64 * 256; idx += 256) {
        int tt = idx >> 14;
        int r  = idx & 16383;
        int k  = r >> 8, j = r & 255;
        int o  = (tt == 0) ? 0 : (tt == 1) ? 512 : 768;  // i, g, o offsets
        Ws[idx] = __ldg(&Wih2[(size_t)(o + j) * 64 + k]);
    }
    for (int idx = tid; idx < 2048; idx += 256) {
        int bb = idx >> 6, k = idx & 63;
        hact[k * 32 + bb] = g_h64[(size_t)(bt * 32 + bb) * 64 + k];
    }
    __syncthreads();

    const int w = tid >> 5, l = tid & 31;
    for (int jc = 0; jc < 4; jc++) {
        int j = jc * 64 + 2 * l;
        ull bI = pk(__ldg(&b2[j]),       __ldg(&b2[j + 1]));
        ull bG = pk(__ldg(&b2[512 + j]), __ldg(&b2[512 + j + 1]));
        ull bO = pk(__ldg(&b2[768 + j]), __ldg(&b2[768 + j + 1]));
        ull aI[4], aG[4], aO[4];
        #pragma unroll
        for (int q = 0; q < 4; q++) { aI[q] = bI; aG[q] = bG; aO[q] = bO; }

        #pragma unroll 4
        for (int k = 0; k < 64; k++) {
            float4 a = *reinterpret_cast<const float4*>(hact + k * 32 + 4 * w);
            ull a0 = pk(a.x, a.x), a1 = pk(a.y, a.y);
            ull a2 = pk(a.z, a.z), a3 = pk(a.w, a.w);
            float2 wi = *reinterpret_cast<const float2*>(Ws + k * 256 + j);
            float2 wg = *reinterpret_cast<const float2*>(Ws + 16384 + k * 256 + j);
            float2 wo = *reinterpret_cast<const float2*>(Ws + 32768 + k * 256 + j);
            ull wpi = pk(wi.x, wi.y), wpg = pk(wg.x, wg.y), wpo = pk(wo.x, wo.y);
            fma2(aI[0], wpi, a0); fma2(aI[1], wpi, a1);
            fma2(aI[2], wpi, a2); fma2(aI[3], wpi, a3);
            fma2(aG[0], wpg, a0); fma2(aG[1], wpg, a1);
            fma2(aG[2], wpg, a2); fma2(aG[3], wpg, a3);
            fma2(aO[0], wpo, a0); fma2(aO[1], wpo, a1);
            fma2(aO[2], wpo, a2); fma2(aO[3], wpo, a3);
        }
        #pragma unroll
        for (int q = 0; q < 4; q++) {
            float2 vi = upk(aI[q]);
            float2 vg = upk(aG[q]);
            float2 vo = upk(aO[q]);
            float c0 = sigf(vi.x) * tanh_(vg.x);
            float h0 = sigf(vo.x) * tanh_(c0);
            float c1 = sigf(vi.y) * tanh_(vg.y);
            float h1 = sigf(vo.y) * tanh_(c1);
            int bb = bt * 32 + 4 * w + q;
            *reinterpret_cast<float2*>(&g_h256[(size_t)bb * 256 + j]) =
                make_float2(h0, h1);
        }
    }
}

// ---------------- output projection: out = h256 @ Wout^T + bout ----------------
__global__ void __launch_bounds__(256)
out_kernel(const float* __restrict__ Wout, const float* __restrict__ bout,
           float* __restrict__ out)
{
    int gw = (blockIdx.x * 256 + threadIdx.x) >> 5;   // one warp per batch elem
    int l  = threadIdx.x & 31;
    if (gw >= 4096) return;
    const float* hrow = g_h256 + (size_t)gw * 256;
    float p0 = 0.0f, p1 = 0.0f;
    #pragma unroll
    for (int m = 0; m < 8; m++) {
        int j = l + 32 * m;
        float h = hrow[j];
        p0 = fmaf(h, __ldg(&Wout[j]), p0);
        p1 = fmaf(h, __ldg(&Wout[256 + j]), p1);
    }
    #pragma unroll
    for (int s = 16; s > 0; s >>= 1) {
        p0 += __shfl_xor_sync(0xffffffffu, p0, s);
        p1 += __shfl_xor_sync(0xffffffffu, p1, s);
    }
    if (l == 0) {
        out[gw * 2]     = p0 + __ldg(&bout[0]);
        out[gw * 2 + 1] = p1 + __ldg(&bout[1]);
    }
}

// ---------------- launch ----------------
extern "C" void kernel_launch(void* const* d_in, const int* in_sizes, int n_in,
                              void* d_out, int out_size)
{
    const float *x = nullptr, *W_embed = nullptr, *Wih1 = nullptr, *Whh1 = nullptr,
                *b1 = nullptr, *Wih2 = nullptr, *b2 = nullptr,
                *Wout = nullptr, *bout = nullptr;
    for (int i = 0; i < n_in; i++) {
        const float* p = (const float*)d_in[i];
        switch (in_sizes[i]) {
            case 4194304: x = p; break;        // (4096, 1024)
            case 40:      W_embed = p; break;  // (20, 2)
            case 5120:    Wih1 = p; break;     // (256, 20)
            case 16384:   Whh1 = p; break;     // (256, 64)
            case 256:     b1 = p; break;       // (256,)
            case 65536:   Wih2 = p; break;     // (1024, 64)
            case 262144:  /* Whh2 unused */ break;
            case 1024:    b2 = p; break;       // (1024,)
            case 512:     Wout = p; break;     // (2, 256)
            case 2:       bout = p; break;     // (2,)
            default: break;
        }
    }
    float* out = (float*)d_out;

    const int SMEM1 = S_TOT * 4;              // 202624 B
    const int SMEM2 = (49152 + 2048) * 4;     // 204800 B
    cudaFuncSetAttribute(lstm1_kernel, cudaFuncAttributeMaxDynamicSharedMemorySize, SMEM1);
    cudaFuncSetAttribute(lstm2_kernel, cudaFuncAttributeMaxDynamicSharedMemorySize, SMEM2);

    lstm1_kernel<<<128, 512, SMEM1>>>(x, W_embed, Wih1, Whh1, b1);
    lstm2_kernel<<<128, 256, SMEM2>>>(Wih2, b2);
    out_kernel<<<512, 256>>>(Wout, bout, out);
    (void)out_size;
}

// round 7
// speedup vs baseline: 1.1030x; 1.1030x over previous
#include <cuda_runtime.h>
#include <cstddef>

typedef unsigned long long ull;

// ---------------- scratch (static device globals; no allocation) ----------------
__device__ float g_h64[4096 * 64];     // LSTM1 final hidden
__device__ float g_h256[4096 * 256];   // LSTM2 hidden

// ---------------- packed f32x2 helpers ----------------
__device__ __forceinline__ ull pk(float lo, float hi) {
    ull r;
    asm("mov.b64 %0, {%1, %2};" : "=l"(r) : "f"(lo), "f"(hi));
    return r;
}
__device__ __forceinline__ void fma2(ull& d, ull a, ull b) {
    asm("fma.rn.f32x2 %0, %1, %2, %0;" : "+l"(d) : "l"(a), "l"(b));
}
__device__ __forceinline__ float2 upk(ull v) {
    float2 r;
    asm("mov.b64 {%0, %1}, %2;" : "=f"(r.x), "=f"(r.y) : "l"(v));
    return r;
}

// accurate activations (expf ~2ulp) — measured rel_err 2e-6 with these
__device__ __forceinline__ float sigf(float x) {
    return __fdividef(1.0f, 1.0f + __expf(-x));
}
__device__ __forceinline__ float tanh_(float x) {
    return __fdividef(2.0f, 1.0f + __expf(-2.0f * x)) - 1.0f;
}

// ---------------- shared layout for LSTM1 (float offsets) ----------------
// Wq   float4[42][128] : 21504 floats  (k-pair packed: {W[2k][j0],W[2k][j0+1],W[2k+1][j0],W[2k+1][j0+1]})
// A2_0 float4[42][33]  :  5544 floats  (act, k-pair packed + batch-dup: {a[2k][b],a[2k][b],a[2k+1][b],a[2k+1][b]}, pad col)
// A2_1 float4[42][33]  :  5544
// bsh  [256], eW [64]
#define S_WQ    0
#define S_ACT0  21504
#define S_ACT1  (S_ACT0 + 5544)
#define S_BSH   (S_ACT1 + 5544)
#define S_EW    (S_BSH + 256)
#define S_TOT   (S_EW + 64)          // 32912 floats = 131648 B
#define A2ROW   33                    // float4 per row (32 batches + 1 pad)

__global__ void __launch_bounds__(256, 1)
lstm1_kernel(const float* __restrict__ x,
             const float* __restrict__ W_embed,
             const float* __restrict__ Wih1,
             const float* __restrict__ Whh1,
             const float* __restrict__ b1)
{
    extern __shared__ float sm[];
    float4* Wq4   = reinterpret_cast<float4*>(sm + S_WQ);
    float*  act0f = sm + S_ACT0;
    float*  act1f = sm + S_ACT1;
    float*  bsh   = sm + S_BSH;
    float*  eW    = sm + S_EW;

    const int tid = threadIdx.x;
    const int bt  = blockIdx.x;          // batch tile (32 elems)

    // combined paired-k weight: col g -> Wih1/Whh1 row g (PyTorch gate order i|f|g|o)
    for (int idx = tid; idx < 42 * 128; idx += 256) {
        int kk = idx >> 7, pj = idx & 127;
        int g0 = 2 * pj;
        int k0 = 2 * kk, k1 = k0 + 1;
        float4 v;
        v.x = (k0 < 20) ? __ldg(&Wih1[g0 * 20 + k0])       : __ldg(&Whh1[g0 * 64 + (k0 - 20)]);
        v.y = (k0 < 20) ? __ldg(&Wih1[(g0+1) * 20 + k0])   : __ldg(&Whh1[(g0+1) * 64 + (k0 - 20)]);
        v.z = (k1 < 20) ? __ldg(&Wih1[g0 * 20 + k1])       : __ldg(&Whh1[g0 * 64 + (k1 - 20)]);
        v.w = (k1 < 20) ? __ldg(&Wih1[(g0+1) * 20 + k1])   : __ldg(&Whh1[(g0+1) * 64 + (k1 - 20)]);
        Wq4[idx] = v;
    }
    bsh[tid] = b1[tid];
    if (tid < 40) eW[tid] = W_embed[tid];
    // zero h rows of act0 (kk 10..41)
    for (int idx = tid; idx < 32 * (A2ROW * 4); idx += 256)
        act0f[10 * (A2ROW * 4) + idx] = 0.0f;
    __syncthreads();

    // ---- mapping (R4): warp w -> batch octet g2 = w&3, j-half jh = w>>2 ----
    const int w  = tid >> 5, l = tid & 31;
    const int g2 = w & 3,  jh = w >> 2;
    const int j0 = jh * 32 + 2 * (l & 15);   // gate pair (within 64-wide type)
    const int b0 = g2 * 8 + 4 * (l >> 4);    // batch quad

    const float4* W4I = Wq4 + (jh * 16 + (l & 15));        // pj for type i
    const float4* W4F = W4I + 32;
    const float4* W4G = W4I + 64;
    const float4* W4O = W4I + 96;

    const ull bI = pk(bsh[j0],       bsh[j0 + 1]);
    const ull bF = pk(bsh[64 + j0],  bsh[64 + j0 + 1]);
    const ull bG = pk(bsh[128 + j0], bsh[128 + j0 + 1]);
    const ull bO = pk(bsh[192 + j0], bsh[192 + j0 + 1]);

    const int kkh = 10 + (j0 >> 1);          // h-row pair index for this thread's (j0, j0+1)

    // register-resident cell state: c[b 0..3][j parity]
    float c0x=0.f,c0y=0.f,c1x=0.f,c1y=0.f,c2x=0.f,c2y=0.f,c3x=0.f,c3y=0.f;

    // embedding duty: each warp owns 4 batches eb0..eb0+3
    const int eb0 = g2 * 8 + jh * 4;
    const float2* xrow = reinterpret_cast<const float2*>(x) +
                         (size_t)(bt * 32 + eb0 + l) * 512;   // deref only for l<4
    float2 tok = make_float2(0.f, 0.f), tok_nxt = make_float2(0.f, 0.f);
    if (l < 4) tok = xrow[0];
    // initial embedding (t=0) into act0 (row e -> kk=e>>1, parity e&1)
    #pragma unroll
    for (int b = 0; b < 4; b++) {
        float tx = __shfl_sync(0xffffffffu, tok.x, b);
        float ty = __shfl_sync(0xffffffffu, tok.y, b);
        if (l < 20) {
            float v = fmaxf(fmaf(tx, eW[2 * l], ty * eW[2 * l + 1]), 0.0f);
            *reinterpret_cast<float2*>(act0f + (l >> 1) * (A2ROW * 4) +
                                       (eb0 + b) * 4 + (l & 1) * 2) = make_float2(v, v);
        }
    }
    if (l < 4) tok_nxt = xrow[1];
    __syncthreads();

#define LOADP(wi,wf,wg,wo,a0,a1,a2,a3, kk) do {                                   \
    wi = *reinterpret_cast<const ulonglong2*>(W4I + (kk) * 128);                  \
    wf = *reinterpret_cast<const ulonglong2*>(W4F + (kk) * 128);                  \
    wg = *reinterpret_cast<const ulonglong2*>(W4G + (kk) * 128);                  \
    wo = *reinterpret_cast<const ulonglong2*>(W4O + (kk) * 128);                  \
    a0 = *reinterpret_cast<const ulonglong2*>(A4 + (kk) * A2ROW);                 \
    a1 = *reinterpret_cast<const ulonglong2*>(A4 + (kk) * A2ROW + 1);             \
    a2 = *reinterpret_cast<const ulonglong2*>(A4 + (kk) * A2ROW + 2);             \
    a3 = *reinterpret_cast<const ulonglong2*>(A4 + (kk) * A2ROW + 3);             \
} while (0)

#define COMPP(wi,wf,wg,wo,a0,a1,a2,a3) do {                                       \
    fma2(accI0, wi.x, a0.x); fma2(accI1, wi.x, a1.x);                             \
    fma2(accI2, wi.x, a2.x); fma2(accI3, wi.x, a3.x);                             \
    fma2(accF0, wf.x, a0.x); fma2(accF1, wf.x, a1.x);                             \
    fma2(accF2, wf.x, a2.x); fma2(accF3, wf.x, a3.x);                             \
    fma2(accG0, wg.x, a0.x); fma2(accG1, wg.x, a1.x);                             \
    fma2(accG2, wg.x, a2.x); fma2(accG3, wg.x, a3.x);                             \
    fma2(accO0, wo.x, a0.x); fma2(accO1, wo.x, a1.x);                             \
    fma2(accO2, wo.x, a2.x); fma2(accO3, wo.x, a3.x);                             \
    fma2(accI0, wi.y, a0.y); fma2(accI1, wi.y, a1.y);                             \
    fma2(accI2, wi.y, a2.y); fma2(accI3, wi.y, a3.y);                             \
    fma2(accF0, wf.y, a0.y); fma2(accF1, wf.y, a1.y);                             \
    fma2(accF2, wf.y, a2.y); fma2(accF3, wf.y, a3.y);                             \
    fma2(accG0, wg.y, a0.y); fma2(accG1, wg.y, a1.y);                             \
    fma2(accG2, wg.y, a2.y); fma2(accG3, wg.y, a3.y);                             \
    fma2(accO0, wo.y, a0.y); fma2(accO1, wo.y, a1.y);                             \
    fma2(accO2, wo.y, a2.y); fma2(accO3, wo.y, a3.y);                             \
} while (0)

    for (int t = 0; t < 512; t++) {
        float* curf = (t & 1) ? act1f : act0f;
        float* nxtf = (t & 1) ? act0f : act1f;
        const float4* A4 = reinterpret_cast<const float4*>(curf) + b0;

        ull accI0=bI,accI1=bI,accI2=bI,accI3=bI;
        ull accF0=bF,accF1=bF,accF2=bF,accF3=bF;
        ull accG0=bG,accG1=bG,accG2=bG,accG3=bG;
        ull accO0=bO,accO1=bO,accO2=bO,accO3=bO;

        // software-pipelined k-pair loop (42 pairs)
        ulonglong2 wiA,wfA,wgA,woA,a0A,a1A,a2A,a3A;
        ulonglong2 wiB,wfB,wgB,woB,a0B,a1B,a2B,a3B;
        LOADP(wiA,wfA,wgA,woA,a0A,a1A,a2A,a3A, 0);
        #pragma unroll 5
        for (int kk = 0; kk < 40; kk += 2) {
            LOADP(wiB,wfB,wgB,woB,a0B,a1B,a2B,a3B, kk + 1);
            COMPP(wiA,wfA,wgA,woA,a0A,a1A,a2A,a3A);
            LOADP(wiA,wfA,wgA,woA,a0A,a1A,a2A,a3A, kk + 2);
            COMPP(wiB,wfB,wgB,woB,a0B,a1B,a2B,a3B);
        }
        LOADP(wiB,wfB,wgB,woB,a0B,a1B,a2B,a3B, 41);
        COMPP(wiA,wfA,wgA,woA,a0A,a1A,a2A,a3A);
        COMPP(wiB,wfB,wgB,woB,a0B,a1B,a2B,a3B);

        // fused pointwise (lane-private; cell state in registers)
        float2 vi, vf, vg, vo;
        float h0x,h0y,h1x,h1y,h2x,h2y,h3x,h3y;
        vi=upk(accI0); vf=upk(accF0); vg=upk(accG0); vo=upk(accO0);
        c0x = fmaf(sigf(vf.x), c0x, sigf(vi.x) * tanh_(vg.x));
        h0x = sigf(vo.x) * tanh_(c0x);
        c0y = fmaf(sigf(vf.y), c0y, sigf(vi.y) * tanh_(vg.y));
        h0y = sigf(vo.y) * tanh_(c0y);
        vi=upk(accI1); vf=upk(accF1); vg=upk(accG1); vo=upk(accO1);
        c1x = fmaf(sigf(vf.x), c1x, sigf(vi.x) * tanh_(vg.x));
        h1x = sigf(vo.x) * tanh_(c1x);
        c1y = fmaf(sigf(vf.y), c1y, sigf(vi.y) * tanh_(vg.y));
        h1y = sigf(vo.y) * tanh_(c1y);
        vi=upk(accI2); vf=upk(accF2); vg=upk(accG2); vo=upk(accO2);
        c2x = fmaf(sigf(vf.x), c2x, sigf(vi.x) * tanh_(vg.x));
        h2x = sigf(vo.x) * tanh_(c2x);
        c2y = fmaf(sigf(vf.y), c2y, sigf(vi.y) * tanh_(vg.y));
        h2y = sigf(vo.y) * tanh_(c2y);
        vi=upk(accI3); vf=upk(accF3); vg=upk(accG3); vo=upk(accO3);
        c3x = fmaf(sigf(vf.x), c3x, sigf(vi.x) * tanh_(vg.x));
        h3x = sigf(vo.x) * tanh_(c3x);
        c3y = fmaf(sigf(vf.y), c3y, sigf(vi.y) * tanh_(vg.y));
        h3y = sigf(vo.y) * tanh_(c3y);

        // h stores into paired-k layout: one STS.128 per batch (4 total)
        {
            float4* N4 = reinterpret_cast<float4*>(nxtf) + kkh * A2ROW + b0;
            N4[0] = make_float4(h0x, h0x, h0y, h0y);
            N4[1] = make_float4(h1x, h1x, h1y, h1y);
            N4[2] = make_float4(h2x, h2x, h2y, h2y);
            N4[3] = make_float4(h3x, h3x, h3y, h3y);
        }

        // per-warp embedding for t+1 (token prefetched a full step ahead)
        if (t < 511) {
            #pragma unroll
            for (int b = 0; b < 4; b++) {
                float tx = __shfl_sync(0xffffffffu, tok_nxt.x, b);
                float ty = __shfl_sync(0xffffffffu, tok_nxt.y, b);
                if (l < 20) {
                    float v = fmaxf(fmaf(tx, eW[2 * l], ty * eW[2 * l + 1]), 0.0f);
                    *reinterpret_cast<float2*>(nxtf + (l >> 1) * (A2ROW * 4) +
                                               (eb0 + b) * 4 + (l & 1) * 2) =
                        make_float2(v, v);
                }
            }
            if (l < 4 && t < 510) tok_nxt = xrow[t + 2];
        }
        __syncthreads();
    }

    // final h (after step 512) lives in act0 (t=511 odd -> nxt=act0)
    for (int idx = tid; idx < 2048; idx += 256) {
        int bb = idx >> 6, j = idx & 63;
        g_h64[(size_t)(bt * 32 + bb) * 64 + j] =
            act0f[((20 + j) >> 1) * (A2ROW * 4) + bb * 4 + (j & 1) * 2];
    }
#undef LOADP
#undef COMPP
}

// ---------------- LSTM2: single step, zero state -> f gate & Whh2 unused ----------------
__global__ void __launch_bounds__(256, 1)
lstm2_kernel(const float* __restrict__ Wih2, const float* __restrict__ b2)
{
    extern __shared__ float sm[];
    float* Ws   = sm;            // [type][k][j], type 0:i 1:g 2:o
    float* hact = sm + 49152;    // [k][b]
    const int tid = threadIdx.x;
    const int bt  = blockIdx.x;

    for (int idx = tid; idx < 3 * 64 * 256; idx += 256) {
        int tt = idx >> 14;
        int r  = idx & 16383;
        int k  = r >> 8, j = r & 255;
        int o  = (tt == 0) ? 0 : (tt == 1) ? 512 : 768;  // i, g, o offsets
        Ws[idx] = __ldg(&Wih2[(size_t)(o + j) * 64 + k]);
    }
    for (int idx = tid; idx < 2048; idx += 256) {
        int bb = idx >> 6, k = idx & 63;
        hact[k * 32 + bb] = g_h64[(size_t)(bt * 32 + bb) * 64 + k];
    }
    __syncthreads();

    const int w = tid >> 5, l = tid & 31;
    for (int jc = 0; jc < 4; jc++) {
        int j = jc * 64 + 2 * l;
        ull bI = pk(__ldg(&b2[j]),       __ldg(&b2[j + 1]));
        ull bG = pk(__ldg(&b2[512 + j]), __ldg(&b2[512 + j + 1]));
        ull bO = pk(__ldg(&b2[768 + j]), __ldg(&b2[768 + j + 1]));
        ull aI[4], aG[4], aO[4];
        #pragma unroll
        for (int q = 0; q < 4; q++) { aI[q] = bI; aG[q] = bG; aO[q] = bO; }

        #pragma unroll 4
        for (int k = 0; k < 64; k++) {
            float4 a = *reinterpret_cast<const float4*>(hact + k * 32 + 4 * w);
            ull a0 = pk(a.x, a.x), a1 = pk(a.y, a.y);
            ull a2 = pk(a.z, a.z), a3 = pk(a.w, a.w);
            float2 wi = *reinterpret_cast<const float2*>(Ws + k * 256 + j);
            float2 wg = *reinterpret_cast<const float2*>(Ws + 16384 + k * 256 + j);
            float2 wo = *reinterpret_cast<const float2*>(Ws + 32768 + k * 256 + j);
            ull wpi = pk(wi.x, wi.y), wpg = pk(wg.x, wg.y), wpo = pk(wo.x, wo.y);
            fma2(aI[0], wpi, a0); fma2(aI[1], wpi, a1);
            fma2(aI[2], wpi, a2); fma2(aI[3], wpi, a3);
            fma2(aG[0], wpg, a0); fma2(aG[1], wpg, a1);
            fma2(aG[2], wpg, a2); fma2(aG[3], wpg, a3);
            fma2(aO[0], wpo, a0); fma2(aO[1], wpo, a1);
            fma2(aO[2], wpo, a2); fma2(aO[3], wpo, a3);
        }
        #pragma unroll
        for (int q = 0; q < 4; q++) {
            float2 vi = upk(aI[q]);
            float2 vg = upk(aG[q]);
            float2 vo = upk(aO[q]);
            float c0 = sigf(vi.x) * tanh_(vg.x);
            float h0 = sigf(vo.x) * tanh_(c0);
            float c1 = sigf(vi.y) * tanh_(vg.y);
            float h1 = sigf(vo.y) * tanh_(c1);
            int bb = bt * 32 + 4 * w + q;
            *reinterpret_cast<float2*>(&g_h256[(size_t)bb * 256 + j]) =
                make_float2(h0, h1);
        }
    }
}

// ---------------- output projection: out = h256 @ Wout^T + bout ----------------
__global__ void __launch_bounds__(256)
out_kernel(const float* __restrict__ Wout, const float* __restrict__ bout,
           float* __restrict__ out)
{
    int gw = (blockIdx.x * 256 + threadIdx.x) >> 5;   // one warp per batch elem
    int l  = threadIdx.x & 31;
    if (gw >= 4096) return;
    const float* hrow = g_h256 + (size_t)gw * 256;
    float p0 = 0.0f, p1 = 0.0f;
    #pragma unroll
    for (int m = 0; m < 8; m++) {
        int j = l + 32 * m;
        float h = hrow[j];
        p0 = fmaf(h, __ldg(&Wout[j]), p0);
        p1 = fmaf(h, __ldg(&Wout[256 + j]), p1);
    }
    #pragma unroll
    for (int s = 16; s > 0; s >>= 1) {
        p0 += __shfl_xor_sync(0xffffffffu, p0, s);
        p1 += __shfl_xor_sync(0xffffffffu, p1, s);
    }
    if (l == 0) {
        out[gw * 2]     = p0 + __ldg(&bout[0]);
        out[gw * 2 + 1] = p1 + __ldg(&bout[1]);
    }
}

// ---------------- launch ----------------
extern "C" void kernel_launch(void* const* d_in, const int* in_sizes, int n_in,
                              void* d_out, int out_size)
{
    const float *x = nullptr, *W_embed = nullptr, *Wih1 = nullptr, *Whh1 = nullptr,
                *b1 = nullptr, *Wih2 = nullptr, *b2 = nullptr,
                *Wout = nullptr, *bout = nullptr;
    for (int i = 0; i < n_in; i++) {
        const float* p = (const float*)d_in[i];
        switch (in_sizes[i]) {
            case 4194304: x = p; break;        // (4096, 1024)
            case 40:      W_embed = p; break;  // (20, 2)
            case 5120:    Wih1 = p; break;     // (256, 20)
            case 16384:   Whh1 = p; break;     // (256, 64)
            case 256:     b1 = p; break;       // (256,)
            case 65536:   Wih2 = p; break;     // (1024, 64)
            case 262144:  /* Whh2 unused */ break;
            case 1024:    b2 = p; break;       // (1024,)
            case 512:     Wout = p; break;     // (2, 256)
            case 2:       bout = p; break;     // (2,)
            default: break;
        }
    }
    float* out = (float*)d_out;

    const int SMEM1 = S_TOT * 4;              // 131648 B
    const int SMEM2 = (49152 + 2048) * 4;     // 204800 B
    cudaFuncSetAttribute(lstm1_kernel, cudaFuncAttributeMaxDynamicSharedMemorySize, SMEM1);
    cudaFuncSetAttribute(lstm2_kernel, cudaFuncAttributeMaxDynamicSharedMemorySize, SMEM2);

    lstm1_kernel<<<128, 256, SMEM1>>>(x, W_embed, Wih1, Whh1, b1);
    lstm2_kernel<<<128, 256, SMEM2>>>(Wih2, b2);
    out_kernel<<<512, 256>>>(Wout, bout, out);
    (void)out_size;
}

// round 8
// speedup vs baseline: 1.1540x; 1.0462x over previous
#include <cuda_runtime.h>
#include <cstddef>

typedef unsigned long long ull;

// ---------------- scratch (static device globals; no allocation) ----------------
__device__ float g_h64[4096 * 64];     // LSTM1 final hidden
__device__ float g_h256[4096 * 256];   // LSTM2 hidden

// ---------------- packed f32x2 helpers ----------------
__device__ __forceinline__ ull pk(float lo, float hi) {
    ull r;
    asm("mov.b64 %0, {%1, %2};" : "=l"(r) : "f"(lo), "f"(hi));
    return r;
}
__device__ __forceinline__ void fma2(ull& d, ull a, ull b) {
    asm("fma.rn.f32x2 %0, %1, %2, %0;" : "+l"(d) : "l"(a), "l"(b));
}
__device__ __forceinline__ float2 upk(ull v) {
    float2 r;
    asm("mov.b64 {%0, %1}, %2;" : "=f"(r.x), "=f"(r.y) : "l"(v));
    return r;
}

// accurate activations (expf ~2ulp) — measured rel_err 2e-6 with these
__device__ __forceinline__ float sigf(float x) {
    return __fdividef(1.0f, 1.0f + __expf(-x));
}
__device__ __forceinline__ float tanh_(float x) {
    return __fdividef(2.0f, 1.0f + __expf(-2.0f * x)) - 1.0f;
}

// ---------------- shared layout for LSTM1 (float offsets) ----------------
// Wq   float4[42][128]        : 21504 floats (k-pair packed weights)
// ACT  float4[2 grp][2 buf][42][17] : 4*714 float4 = 11424 floats
//      (act, k-pair packed + dup: {a[2k][b],a[2k][b],a[2k+1][b],a[2k+1][b]}, 16 batches + pad)
// bsh [256], eW [64]
#define S_WQ    0
#define S_ACT   21504
#define S_BSH   (S_ACT + 11424)      // 32928
#define S_EW    (S_BSH + 256)        // 33184
#define S_TOT   (S_EW + 64)          // 33248 floats = 132992 B
#define A2ROW   17                    // float4 per row (16 batches + 1 pad)
#define ABUF    714                   // float4 per buffer (42 * 17)

__global__ void __launch_bounds__(256, 1)
lstm1_kernel(const float* __restrict__ x,
             const float* __restrict__ W_embed,
             const float* __restrict__ Wih1,
             const float* __restrict__ Whh1,
             const float* __restrict__ b1)
{
    extern __shared__ float sm[];
    float4* Wq4  = reinterpret_cast<float4*>(sm + S_WQ);
    float4* ACT4 = reinterpret_cast<float4*>(sm + S_ACT);
    float*  bsh  = sm + S_BSH;
    float*  eW   = sm + S_EW;

    const int tid = threadIdx.x;
    const int bt  = blockIdx.x;          // batch tile (32 elems)

    // combined paired-k weight (gate order i|f|g|o)
    for (int idx = tid; idx < 42 * 128; idx += 256) {
        int kk = idx >> 7, pj = idx & 127;
        int g0 = 2 * pj;
        int k0 = 2 * kk, k1 = k0 + 1;
        float4 v;
        v.x = (k0 < 20) ? __ldg(&Wih1[g0 * 20 + k0])     : __ldg(&Whh1[g0 * 64 + (k0 - 20)]);
        v.y = (k0 < 20) ? __ldg(&Wih1[(g0+1) * 20 + k0]) : __ldg(&Whh1[(g0+1) * 64 + (k0 - 20)]);
        v.z = (k1 < 20) ? __ldg(&Wih1[g0 * 20 + k1])     : __ldg(&Whh1[g0 * 64 + (k1 - 20)]);
        v.w = (k1 < 20) ? __ldg(&Wih1[(g0+1) * 20 + k1]) : __ldg(&Whh1[(g0+1) * 64 + (k1 - 20)]);
        Wq4[idx] = v;
    }
    bsh[tid] = b1[tid];
    if (tid < 40) eW[tid] = W_embed[tid];
    // zero all act buffers (covers h rows of both groups' buffer 0)
    for (int idx = tid; idx < 4 * ABUF; idx += 256)
        ACT4[idx] = make_float4(0.f, 0.f, 0.f, 0.f);
    __syncthreads();

    // ---- mapping ----
    // warp w: group grp = w>>2 (16 batches each), wl = w&3 -> oct = wl&1, jh = wl>>1
    // lane: j0 = jh*32 + 2*(l&15) gate pair; b0 = oct*8 + 4*(l>>4) batch quad (within group)
    const int w   = tid >> 5, l = tid & 31;
    const int grp = w >> 2,  wl = w & 3;
    const int oct = wl & 1,  jh = wl >> 1;
    const int j0  = jh * 32 + 2 * (l & 15);
    const int b0  = oct * 8 + 4 * (l >> 4);
    const int barid = 1 + grp;

    float4* actG0 = ACT4 + (grp * 2) * ABUF;       // buffer parity 0
    float4* actG1 = actG0 + ABUF;                  // buffer parity 1

    const float4* W4I = Wq4 + (jh * 16 + (l & 15));
    const float4* W4F = W4I + 32;
    const float4* W4G = W4I + 64;
    const float4* W4O = W4I + 96;

    const ull bI = pk(bsh[j0],       bsh[j0 + 1]);
    const ull bF = pk(bsh[64 + j0],  bsh[64 + j0 + 1]);
    const ull bG = pk(bsh[128 + j0], bsh[128 + j0 + 1]);
    const ull bO = pk(bsh[192 + j0], bsh[192 + j0 + 1]);

    const int kkh = 10 + (j0 >> 1);      // h-row pair index for (j0, j0+1)

    // register-resident cell state
    float c0x=0.f,c0y=0.f,c1x=0.f,c1y=0.f,c2x=0.f,c2y=0.f,c3x=0.f,c3y=0.f;

    // embedding duty: warp wl owns group-local batches wl*4 .. wl*4+3
    const int eb0 = wl * 4;
    const float2* xrow = reinterpret_cast<const float2*>(x) +
                         (size_t)(bt * 32 + grp * 16 + eb0 + l) * 512;  // deref only l<4
    float2 tok = make_float2(0.f, 0.f), tok_nxt = make_float2(0.f, 0.f);
    if (l < 4) tok = xrow[0];
    // initial embedding (t=0) into group buffer 0
    {
        float* a0f = reinterpret_cast<float*>(actG0);
        #pragma unroll
        for (int b = 0; b < 4; b++) {
            float tx = __shfl_sync(0xffffffffu, tok.x, b);
            float ty = __shfl_sync(0xffffffffu, tok.y, b);
            if (l < 20) {
                float v = fmaxf(fmaf(tx, eW[2 * l], ty * eW[2 * l + 1]), 0.0f);
                *reinterpret_cast<float2*>(a0f + (l >> 1) * (A2ROW * 4) +
                                           (eb0 + b) * 4 + (l & 1) * 2) = make_float2(v, v);
            }
        }
    }
    if (l < 4) tok_nxt = xrow[1];
    asm volatile("bar.sync %0, 128;" :: "r"(barid) : "memory");

#define LOADP(wi,wf,wg,wo,a0,a1,a2,a3, kk) do {                                   \
    wi = *reinterpret_cast<const ulonglong2*>(W4I + (kk) * 128);                  \
    wf = *reinterpret_cast<const ulonglong2*>(W4F + (kk) * 128);                  \
    wg = *reinterpret_cast<const ulonglong2*>(W4G + (kk) * 128);                  \
    wo = *reinterpret_cast<const ulonglong2*>(W4O + (kk) * 128);                  \
    a0 = *reinterpret_cast<const ulonglong2*>(A4 + (kk) * A2ROW);                 \
    a1 = *reinterpret_cast<const ulonglong2*>(A4 + (kk) * A2ROW + 1);             \
    a2 = *reinterpret_cast<const ulonglong2*>(A4 + (kk) * A2ROW + 2);             \
    a3 = *reinterpret_cast<const ulonglong2*>(A4 + (kk) * A2ROW + 3);             \
} while (0)

#define COMPP(wi,wf,wg,wo,a0,a1,a2,a3) do {                                       \
    fma2(accI0, wi.x, a0.x); fma2(accI1, wi.x, a1.x);                             \
    fma2(accI2, wi.x, a2.x); fma2(accI3, wi.x, a3.x);                             \
    fma2(accF0, wf.x, a0.x); fma2(accF1, wf.x, a1.x);                             \
    fma2(accF2, wf.x, a2.x); fma2(accF3, wf.x, a3.x);                             \
    fma2(accG0, wg.x, a0.x); fma2(accG1, wg.x, a1.x);                             \
    fma2(accG2, wg.x, a2.x); fma2(accG3, wg.x, a3.x);                             \
    fma2(accO0, wo.x, a0.x); fma2(accO1, wo.x, a1.x);                             \
    fma2(accO2, wo.x, a2.x); fma2(accO3, wo.x, a3.x);                             \
    fma2(accI0, wi.y, a0.y); fma2(accI1, wi.y, a1.y);                             \
    fma2(accI2, wi.y, a2.y); fma2(accI3, wi.y, a3.y);                             \
    fma2(accF0, wf.y, a0.y); fma2(accF1, wf.y, a1.y);                             \
    fma2(accF2, wf.y, a2.y); fma2(accF3, wf.y, a3.y);                             \
    fma2(accG0, wg.y, a0.y); fma2(accG1, wg.y, a1.y);                             \
    fma2(accG2, wg.y, a2.y); fma2(accG3, wg.y, a3.y);                             \
    fma2(accO0, wo.y, a0.y); fma2(accO1, wo.y, a1.y);                             \
    fma2(accO2, wo.y, a2.y); fma2(accO3, wo.y, a3.y);                             \
} while (0)

    for (int t = 0; t < 512; t++) {
        float4* cur4 = (t & 1) ? actG1 : actG0;
        float4* nxt4 = (t & 1) ? actG0 : actG1;
        const float4* A4 = cur4 + b0;

        ull accI0=bI,accI1=bI,accI2=bI,accI3=bI;
        ull accF0=bF,accF1=bF,accF2=bF,accF3=bF;
        ull accG0=bG,accG1=bG,accG2=bG,accG3=bG;
        ull accO0=bO,accO1=bO,accO2=bO,accO3=bO;

        // software-pipelined k-pair loop (42 pairs)
        ulonglong2 wiA,wfA,wgA,woA,a0A,a1A,a2A,a3A;
        ulonglong2 wiB,wfB,wgB,woB,a0B,a1B,a2B,a3B;
        LOADP(wiA,wfA,wgA,woA,a0A,a1A,a2A,a3A, 0);
        #pragma unroll 5
        for (int kk = 0; kk < 40; kk += 2) {
            LOADP(wiB,wfB,wgB,woB,a0B,a1B,a2B,a3B, kk + 1);
            COMPP(wiA,wfA,wgA,woA,a0A,a1A,a2A,a3A);
            LOADP(wiA,wfA,wgA,woA,a0A,a1A,a2A,a3A, kk + 2);
            COMPP(wiB,wfB,wgB,woB,a0B,a1B,a2B,a3B);
        }
        LOADP(wiB,wfB,wgB,woB,a0B,a1B,a2B,a3B, 41);
        COMPP(wiA,wfA,wgA,woA,a0A,a1A,a2A,a3A);
        COMPP(wiB,wfB,wgB,woB,a0B,a1B,a2B,a3B);

        // fused pointwise (lane-private; cell state in registers)
        float2 vi, vf, vg, vo;
        float h0x,h0y,h1x,h1y,h2x,h2y,h3x,h3y;
        vi=upk(accI0); vf=upk(accF0); vg=upk(accG0); vo=upk(accO0);
        c0x = fmaf(sigf(vf.x), c0x, sigf(vi.x) * tanh_(vg.x));
        h0x = sigf(vo.x) * tanh_(c0x);
        c0y = fmaf(sigf(vf.y), c0y, sigf(vi.y) * tanh_(vg.y));
        h0y = sigf(vo.y) * tanh_(c0y);
        vi=upk(accI1); vf=upk(accF1); vg=upk(accG1); vo=upk(accO1);
        c1x = fmaf(sigf(vf.x), c1x, sigf(vi.x) * tanh_(vg.x));
        h1x = sigf(vo.x) * tanh_(c1x);
        c1y = fmaf(sigf(vf.y), c1y, sigf(vi.y) * tanh_(vg.y));
        h1y = sigf(vo.y) * tanh_(c1y);
        vi=upk(accI2); vf=upk(accF2); vg=upk(accG2); vo=upk(accO2);
        c2x = fmaf(sigf(vf.x), c2x, sigf(vi.x) * tanh_(vg.x));
        h2x = sigf(vo.x) * tanh_(c2x);
        c2y = fmaf(sigf(vf.y), c2y, sigf(vi.y) * tanh_(vg.y));
        h2y = sigf(vo.y) * tanh_(c2y);
        vi=upk(accI3); vf=upk(accF3); vg=upk(accG3); vo=upk(accO3);
        c3x = fmaf(sigf(vf.x), c3x, sigf(vi.x) * tanh_(vg.x));
        h3x = sigf(vo.x) * tanh_(c3x);
        c3y = fmaf(sigf(vf.y), c3y, sigf(vi.y) * tanh_(vg.y));
        h3y = sigf(vo.y) * tanh_(c3y);

        // h stores into paired-k layout: one STS.128 per batch (4 total)
        {
            float4* N4 = nxt4 + kkh * A2ROW + b0;
            N4[0] = make_float4(h0x, h0x, h0y, h0y);
            N4[1] = make_float4(h1x, h1x, h1y, h1y);
            N4[2] = make_float4(h2x, h2x, h2y, h2y);
            N4[3] = make_float4(h3x, h3x, h3y, h3y);
        }

        // per-warp embedding for t+1 (token prefetched a full step ahead)
        if (t < 511) {
            float* nxtf = reinterpret_cast<float*>(nxt4);
            #pragma unroll
            for (int b = 0; b < 4; b++) {
                float tx = __shfl_sync(0xffffffffu, tok_nxt.x, b);
                float ty = __shfl_sync(0xffffffffu, tok_nxt.y, b);
                if (l < 20) {
                    float v = fmaxf(fmaf(tx, eW[2 * l], ty * eW[2 * l + 1]), 0.0f);
                    *reinterpret_cast<float2*>(nxtf + (l >> 1) * (A2ROW * 4) +
                                               (eb0 + b) * 4 + (l & 1) * 2) =
                        make_float2(v, v);
                }
            }
            if (l < 4 && t < 510) tok_nxt = xrow[t + 2];
        }
        // group-local barrier — the two 4-warp groups run decoupled
        asm volatile("bar.sync %0, 128;" :: "r"(barid) : "memory");
    }

    // final h (after step 512) lives in buffer 0 (t=511 odd -> nxt = actG0)
    {
        const float* a0f = reinterpret_cast<const float*>(actG0);
        int tig = tid & 127;                 // thread index within group
        for (int idx = tig; idx < 1024; idx += 128) {
            int bb = idx >> 6, j = idx & 63;
            g_h64[(size_t)(bt * 32 + grp * 16 + bb) * 64 + j] =
                a0f[((20 + j) >> 1) * (A2ROW * 4) + bb * 4 + (j & 1) * 2];
        }
    }
#undef LOADP
#undef COMPP
}

// ---------------- LSTM2: single step, zero state -> f gate & Whh2 unused ----------------
__global__ void __launch_bounds__(256, 1)
lstm2_kernel(const float* __restrict__ Wih2, const float* __restrict__ b2)
{
    extern __shared__ float sm[];
    float* Ws   = sm;            // [type][k][j], type 0:i 1:g 2:o
    float* hact = sm + 49152;    // [k][b]
    const int tid = threadIdx.x;
    const int bt  = blockIdx.x;

    for (int idx = tid; idx < 3 * 64 * 256; idx += 256) {
        int tt = idx >> 14;
        int r  = idx & 16383;
        int k  = r >> 8, j = r & 255;
        int o  = (tt == 0) ? 0 : (tt == 1) ? 512 : 768;  // i, g, o offsets
        Ws[idx] = __ldg(&Wih2[(size_t)(o + j) * 64 + k]);
    }
    for (int idx = tid; idx < 2048; idx += 256) {
        int bb = idx >> 6, k = idx & 63;
        hact[k * 32 + bb] = g_h64[(size_t)(bt * 32 + bb) * 64 + k];
    }
    __syncthreads();

    const int w = tid >> 5, l = tid & 31;
    for (int jc = 0; jc < 4; jc++) {
        int j = jc * 64 + 2 * l;
        ull bI = pk(__ldg(&b2[j]),       __ldg(&b2[j + 1]));
        ull bG = pk(__ldg(&b2[512 + j]), __ldg(&b2[512 + j + 1]));
        ull bO = pk(__ldg(&b2[768 + j]), __ldg(&b2[768 + j + 1]));
        ull aI[4], aG[4], aO[4];
        #pragma unroll
        for (int q = 0; q < 4; q++) { aI[q] = bI; aG[q] = bG; aO[q] = bO; }

        #pragma unroll 4
        for (int k = 0; k < 64; k++) {
            float4 a = *reinterpret_cast<const float4*>(hact + k * 32 + 4 * w);
            ull a0 = pk(a.x, a.x), a1 = pk(a.y, a.y);
            ull a2 = pk(a.z, a.z), a3 = pk(a.w, a.w);
            float2 wi = *reinterpret_cast<const float2*>(Ws + k * 256 + j);
            float2 wg = *reinterpret_cast<const float2*>(Ws + 16384 + k * 256 + j);
            float2 wo = *reinterpret_cast<const float2*>(Ws + 32768 + k * 256 + j);
            ull wpi = pk(wi.x, wi.y), wpg = pk(wg.x, wg.y), wpo = pk(wo.x, wo.y);
            fma2(aI[0], wpi, a0); fma2(aI[1], wpi, a1);
            fma2(aI[2], wpi, a2); fma2(aI[3], wpi, a3);
            fma2(aG[0], wpg, a0); fma2(aG[1], wpg, a1);
            fma2(aG[2], wpg, a2); fma2(aG[3], wpg, a3);
            fma2(aO[0], wpo, a0); fma2(aO[1], wpo, a1);
            fma2(aO[2], wpo, a2); fma2(aO[3], wpo, a3);
        }
        #pragma unroll
        for (int q = 0; q < 4; q++) {
            float2 vi = upk(aI[q]);
            float2 vg = upk(aG[q]);
            float2 vo = upk(aO[q]);
            float c0 = sigf(vi.x) * tanh_(vg.x);
            float h0 = sigf(vo.x) * tanh_(c0);
            float c1 = sigf(vi.y) * tanh_(vg.y);
            float h1 = sigf(vo.y) * tanh_(c1);
            int bb = bt * 32 + 4 * w + q;
            *reinterpret_cast<float2*>(&g_h256[(size_t)bb * 256 + j]) =
                make_float2(h0, h1);
        }
    }
}

// ---------------- output projection: out = h256 @ Wout^T + bout ----------------
__global__ void __launch_bounds__(256)
out_kernel(const float* __restrict__ Wout, const float* __restrict__ bout,
           float* __restrict__ out)
{
    int gw = (blockIdx.x * 256 + threadIdx.x) >> 5;   // one warp per batch elem
    int l  = threadIdx.x & 31;
    if (gw >= 4096) return;
    const float* hrow = g_h256 + (size_t)gw * 256;
    float p0 = 0.0f, p1 = 0.0f;
    #pragma unroll
    for (int m = 0; m < 8; m++) {
        int j = l + 32 * m;
        float h = hrow[j];
        p0 = fmaf(h, __ldg(&Wout[j]), p0);
        p1 = fmaf(h, __ldg(&Wout[256 + j]), p1);
    }
    #pragma unroll
    for (int s = 16; s > 0; s >>= 1) {
        p0 += __shfl_xor_sync(0xffffffffu, p0, s);
        p1 += __shfl_xor_sync(0xffffffffu, p1, s);
    }
    if (l == 0) {
        out[gw * 2]     = p0 + __ldg(&bout[0]);
        out[gw * 2 + 1] = p1 + __ldg(&bout[1]);
    }
}

// ---------------- launch ----------------
extern "C" void kernel_launch(void* const* d_in, const int* in_sizes, int n_in,
                              void* d_out, int out_size)
{
    const float *x = nullptr, *W_embed = nullptr, *Wih1 = nullptr, *Whh1 = nullptr,
                *b1 = nullptr, *Wih2 = nullptr, *b2 = nullptr,
                *Wout = nullptr, *bout = nullptr;
    for (int i = 0; i < n_in; i++) {
        const float* p = (const float*)d_in[i];
        switch (in_sizes[i]) {
            case 4194304: x = p; break;        // (4096, 1024)
            case 40:      W_embed = p; break;  // (20, 2)
            case 5120:    Wih1 = p; break;     // (256, 20)
            case 16384:   Whh1 = p; break;     // (256, 64)
            case 256:     b1 = p; break;       // (256,)
            case 65536:   Wih2 = p; break;     // (1024, 64)
            case 262144:  /* Whh2 unused */ break;
            case 1024:    b2 = p; break;       // (1024,)
            case 512:     Wout = p; break;     // (2, 256)
            case 2:       bout = p; break;     // (2,)
            default: break;
        }
    }
    float* out = (float*)d_out;

    const int SMEM1 = S_TOT * 4;              // 132992 B
    const int SMEM2 = (49152 + 2048) * 4;     // 204800 B
    cudaFuncSetAttribute(lstm1_kernel, cudaFuncAttributeMaxDynamicSharedMemorySize, SMEM1);
    cudaFuncSetAttribute(lstm2_kernel, cudaFuncAttributeMaxDynamicSharedMemorySize, SMEM2);

    lstm1_kernel<<<128, 256, SMEM1>>>(x, W_embed, Wih1, Whh1, b1);
    lstm2_kernel<<<128, 256, SMEM2>>>(Wih2, b2);
    out_kernel<<<512, 256>>>(Wout, bout, out);
    (void)out_size;
}